// round 13
// baseline (speedup 1.0000x reference)
#include <cuda_runtime.h>
#include <cuda_fp16.h>
#include <math.h>
#include <stdint.h>

#define NN 65536
#define NE 1048576
#define NB 512

// ---------------- scratch (static __device__, no allocation) ----------------
__device__ float  d_x77[NN * 77];
__device__ __half d_h1h[NN * 256];
__device__ float  d_out1[NN * 256];
__device__ float  d_as1[NN * 4];
__device__ float  d_ad1[NN * 4];
__device__ __half d_h2h[NN * 64];
__device__ float  d_out2[NN * 64];
__device__ float  d_as2[NN];
__device__ float  d_ad2[NN];
__device__ int    d_deg[NN];
__device__ int    d_off[NN + 1];
__device__ int    d_cur[NN];
__device__ int    d_bsum[256];
__device__ int    d_boff[256];
__device__ int    d_perm[NE];      // CSR position -> edge id
__device__ int    d_srcp[NE];      // src node id, CSR-permuted
__device__ float4 d_eadot1[NE];    // CSR-permuted edge-attr logit dots
__device__ float  d_eadot2[NE];
__device__ float  d_scene[NB * 128];
__device__ float  d_gate[NN];
__device__ int    d_bs[NB];
__device__ int    d_be[NB];
__device__ float  d_rel[NB * 64];
__device__ float  d_we1[20];   // [k][h] k<5, h<4
__device__ float  d_we2[5];

// ---------------- helpers ----------------
__device__ __forceinline__ float warpSumAll(float v) {
    #pragma unroll
    for (int o = 16; o; o >>= 1) v += __shfl_xor_sync(0xffffffffu, v, o);
    return v;
}
__device__ __forceinline__ float leaky02(float v) { return v > 0.f ? v : 0.2f * v; }

__device__ __forceinline__ uint32_t f2tf32(float f) {
    uint32_t r;
    asm("cvt.rna.tf32.f32 %0, %1;" : "=r"(r) : "f"(f));
    return r;
}
__device__ __forceinline__ void mma_tf32(float c[4], const uint32_t a[4], const uint32_t b[2]) {
    asm volatile(
        "mma.sync.aligned.m16n8k8.row.col.f32.tf32.tf32.f32 "
        "{%0,%1,%2,%3}, {%4,%5,%6,%7}, {%8,%9}, {%0,%1,%2,%3};"
        : "+f"(c[0]), "+f"(c[1]), "+f"(c[2]), "+f"(c[3])
        : "r"(a[0]), "r"(a[1]), "r"(a[2]), "r"(a[3]), "r"(b[0]), "r"(b[1]));
}

// ---------------- tiny precompute: We . att_edge per head ----------------
__global__ void compute_we_kernel(const float* __restrict__ g1We, const float* __restrict__ g1ae,
                                  const float* __restrict__ g2We, const float* __restrict__ g2ae) {
    int t = threadIdx.x;
    if (t < 20) {
        int k = t / 4, h = t % 4;
        float s = 0.f;
        for (int c = 0; c < 64; c++) s += g1We[k * 256 + h * 64 + c] * g1ae[h * 64 + c];
        d_we1[k * 4 + h] = s;
    } else if (t < 25) {
        int k = t - 20;
        float s = 0.f;
        for (int c = 0; c < 64; c++) s += g2We[k * 64 + c] * g2ae[c];
        d_we2[k] = s;
    }
}

// ---------------- tf32 tensor-core GEMM ----------------
// Block tile 128(M) x 64(N) x 32(K). 8 warps 4x2; warp tile 32x32.
// Optional: fp16 output (HOUT), fp32 output (WF32), fused per-row attention
// dots over this block's 64 columns (ATT: attS/attD get dot(row, asrc/adst)).
template <bool RELU, bool BIAS, bool HOUT, bool WF32, bool ATT>
__global__ void gemm_tf32_kernel(const float* __restrict__ A, const float* __restrict__ W,
                                 const float* __restrict__ bias, float* __restrict__ C,
                                 __half* __restrict__ Ch,
                                 const float* __restrict__ asrc, const float* __restrict__ adst,
                                 float* __restrict__ attS, float* __restrict__ attD, int att_stride,
                                 int M, int K, int Nc, int ldc, int coff) {
    __shared__ uint32_t As[128][36];  // [m][k]
    __shared__ uint32_t Ws[32][72];   // [k][n]
    __shared__ float sPs[128];
    __shared__ float sPd[128];
    int tid = threadIdx.x;
    int warp = tid >> 5, lane = tid & 31;
    int wm = warp >> 1, wn = warp & 1;
    int row0 = blockIdx.y * 128, col0 = blockIdx.x * 64;
    int gr = lane >> 2, gc = lane & 3;

    float acc[2][4][4];
    #pragma unroll
    for (int mt = 0; mt < 2; mt++)
        #pragma unroll
        for (int nt = 0; nt < 4; nt++)
            #pragma unroll
            for (int f = 0; f < 4; f++) acc[mt][nt][f] = 0.f;

    int kTiles = (K + 31) >> 5;
    for (int kt = 0; kt < kTiles; kt++) {
        int k0 = kt << 5;
        #pragma unroll
        for (int j = 0; j < 16; j++) {
            int idx = tid + j * 256;
            int m = idx >> 5, k = idx & 31;
            float v = (k0 + k < K) ? A[(long)(row0 + m) * K + k0 + k] : 0.f;
            As[m][k] = f2tf32(v);
        }
        #pragma unroll
        for (int j = 0; j < 8; j++) {
            int idx = tid + j * 256;
            int k = idx >> 6, n = idx & 63;
            float v = (k0 + k < K) ? W[(long)(k0 + k) * Nc + col0 + n] : 0.f;
            Ws[k][n] = f2tf32(v);
        }
        __syncthreads();
        #pragma unroll
        for (int ks = 0; ks < 4; ks++) {
            int kb = ks << 3;
            uint32_t a[2][4];
            #pragma unroll
            for (int mt = 0; mt < 2; mt++) {
                int mr = wm * 32 + mt * 16 + gr;
                a[mt][0] = As[mr][kb + gc];
                a[mt][1] = As[mr + 8][kb + gc];
                a[mt][2] = As[mr][kb + gc + 4];
                a[mt][3] = As[mr + 8][kb + gc + 4];
            }
            uint32_t b[4][2];
            #pragma unroll
            for (int nt = 0; nt < 4; nt++) {
                int nc = wn * 32 + nt * 8 + gr;
                b[nt][0] = Ws[kb + gc][nc];
                b[nt][1] = Ws[kb + gc + 4][nc];
            }
            #pragma unroll
            for (int mt = 0; mt < 2; mt++)
                #pragma unroll
                for (int nt = 0; nt < 4; nt++)
                    mma_tf32(acc[mt][nt], a[mt], b[nt]);
        }
        __syncthreads();
    }
    if (ATT) {
        if (tid < 128) { sPs[tid] = 0.f; sPd[tid] = 0.f; }
        __syncthreads();
    }
    #pragma unroll
    for (int mt = 0; mt < 2; mt++) {
        int rl = wm * 32 + mt * 16 + gr;
        int r0 = row0 + rl;
        float psA = 0.f, pdA = 0.f, psB = 0.f, pdB = 0.f;
        #pragma unroll
        for (int nt = 0; nt < 4; nt++) {
            int cc = col0 + wn * 32 + nt * 8 + gc * 2;
            float b0 = BIAS ? bias[cc] : 0.f;
            float b1 = BIAS ? bias[cc + 1] : 0.f;
            float v0 = acc[mt][nt][0] + b0;
            float v1 = acc[mt][nt][1] + b1;
            float v2 = acc[mt][nt][2] + b0;
            float v3 = acc[mt][nt][3] + b1;
            if (RELU) { v0 = fmaxf(v0, 0.f); v1 = fmaxf(v1, 0.f); v2 = fmaxf(v2, 0.f); v3 = fmaxf(v3, 0.f); }
            if (WF32) {
                C[(long)r0 * ldc + coff + cc]           = v0;
                C[(long)r0 * ldc + coff + cc + 1]       = v1;
                C[(long)(r0 + 8) * ldc + coff + cc]     = v2;
                C[(long)(r0 + 8) * ldc + coff + cc + 1] = v3;
            }
            if (HOUT) {
                *(__half2*)(Ch + (long)r0 * ldc + cc)       = __floats2half2_rn(v0, v1);
                *(__half2*)(Ch + (long)(r0 + 8) * ldc + cc) = __floats2half2_rn(v2, v3);
            }
            if (ATT) {
                float s0 = asrc[cc], s1 = asrc[cc + 1];
                float q0 = adst[cc], q1 = adst[cc + 1];
                psA = fmaf(v0, s0, fmaf(v1, s1, psA));
                pdA = fmaf(v0, q0, fmaf(v1, q1, pdA));
                psB = fmaf(v2, s0, fmaf(v3, s1, psB));
                pdB = fmaf(v2, q0, fmaf(v3, q1, pdB));
            }
        }
        if (ATT) {
            atomicAdd(&sPs[rl], psA);
            atomicAdd(&sPd[rl], pdA);
            atomicAdd(&sPs[rl + 8], psB);
            atomicAdd(&sPd[rl + 8], pdB);
        }
    }
    if (ATT) {
        __syncthreads();
        if (tid < 128) {
            long row = row0 + tid;
            attS[row * att_stride + blockIdx.x] = sPs[tid];
            attD[row * att_stride + blockIdx.x] = sPd[tid];
        }
    }
}

// ---------------- copy x (13 cols) into x77 ----------------
__global__ void copyx_kernel(const float* __restrict__ x) {
    int idx = blockIdx.x * blockDim.x + threadIdx.x;
    if (idx >= NN * 13) return;
    int n = idx / 13, k = idx - n * 13;
    d_x77[n * 77 + k] = x[idx];
}

// ---------------- CSR build (hierarchical scan) ----------------
__global__ void init_kernel() {
    int i = blockIdx.x * blockDim.x + threadIdx.x;
    if (i < NN) d_deg[i] = 0;
    if (i < NB) { d_bs[i] = NN; d_be[i] = 0; }
}
__global__ void hist_kernel(const int* __restrict__ dst) {
    int e = blockIdx.x * blockDim.x + threadIdx.x;
    if (e < NE) atomicAdd(&d_deg[dst[e]], 1);
}
__global__ void blocksum_kernel() {
    __shared__ int sh[8];
    int t = threadIdx.x;
    int v = d_deg[blockIdx.x * 256 + t];
    #pragma unroll
    for (int o = 16; o; o >>= 1) v += __shfl_xor_sync(0xffffffffu, v, o);
    if ((t & 31) == 0) sh[t >> 5] = v;
    __syncthreads();
    if (t < 8) {
        int s = sh[t];
        #pragma unroll
        for (int o = 4; o; o >>= 1) s += __shfl_xor_sync(0xffu, s, o);
        if (t == 0) d_bsum[blockIdx.x] = s;
    }
}
__global__ void scanb_kernel() {
    __shared__ int sh[256];
    int t = threadIdx.x;
    int v = d_bsum[t];
    sh[t] = v;
    __syncthreads();
    #pragma unroll
    for (int o = 1; o < 256; o <<= 1) {
        int u = (t >= o) ? sh[t - o] : 0;
        __syncthreads();
        sh[t] += u;
        __syncthreads();
    }
    d_boff[t] = sh[t] - v;
}
__global__ void expand_kernel() {
    __shared__ int sh[256];
    int t = threadIdx.x;
    int n = blockIdx.x * 256 + t;
    int v = d_deg[n];
    sh[t] = v;
    __syncthreads();
    #pragma unroll
    for (int o = 1; o < 256; o <<= 1) {
        int u = (t >= o) ? sh[t - o] : 0;
        __syncthreads();
        sh[t] += u;
        __syncthreads();
    }
    int off = d_boff[blockIdx.x] + sh[t] - v;
    d_off[n] = off;
    d_cur[n] = off;
    if (n == NN - 1) d_off[NN] = NE;
}
__global__ void scatter_kernel(const int* __restrict__ dst) {
    int e = blockIdx.x * blockDim.x + threadIdx.x;
    if (e >= NE) return;
    int p = atomicAdd(&d_cur[dst[e]], 1);
    d_perm[p] = e;
}
// gather-permute with fused edge-attr dots: coalesced writes, random reads
__global__ void permute_kernel(const int* __restrict__ src, const float* __restrict__ ea) {
    int i = blockIdx.x * blockDim.x + threadIdx.x;
    if (i >= NE) return;
    int e = d_perm[i];
    float a[5];
    #pragma unroll
    for (int k = 0; k < 5; k++) a[k] = ea[e * 5 + k];
    float4 ed = make_float4(0.f, 0.f, 0.f, 0.f);
    float e2 = 0.f;
    #pragma unroll
    for (int k = 0; k < 5; k++) {
        ed.x = fmaf(a[k], d_we1[k * 4 + 0], ed.x);
        ed.y = fmaf(a[k], d_we1[k * 4 + 1], ed.y);
        ed.z = fmaf(a[k], d_we1[k * 4 + 2], ed.z);
        ed.w = fmaf(a[k], d_we1[k * 4 + 3], ed.w);
        e2   = fmaf(a[k], d_we2[k], e2);
    }
    d_srcp[i] = src[e];
    d_eadot1[i] = ed;
    d_eadot2[i] = e2;
}

// ---------------- GAT1 aggregate: single-pass unnormalized softmax ----------------
__global__ void gat1_agg_kernel(const float* __restrict__ bias) {
    int n = (blockIdx.x * blockDim.x + threadIdx.x) >> 5;
    if (n >= NN) return;
    int lane = threadIdx.x & 31;
    int beg = d_off[n], end = d_off[n + 1];
    float4 ad4 = *(const float4*)(d_ad1 + n * 4);
    int h = lane >> 3;
    int gc = lane * 8;
    float acc[8] = {0.f, 0.f, 0.f, 0.f, 0.f, 0.f, 0.f, 0.f};
    float sm[4] = {0.f, 0.f, 0.f, 0.f};
    for (int i0 = beg; i0 < end; i0 += 32) {
        int i = i0 + lane;
        int s_l = 0;
        float4 w_l = make_float4(0.f, 0.f, 0.f, 0.f);
        if (i < end) {
            s_l = d_srcp[i];
            float4 ed = d_eadot1[i];
            float4 as = *(const float4*)(d_as1 + s_l * 4);
            w_l.x = __expf(leaky02(as.x + ed.x + ad4.x));
            w_l.y = __expf(leaky02(as.y + ed.y + ad4.y));
            w_l.z = __expf(leaky02(as.z + ed.z + ad4.z));
            w_l.w = __expf(leaky02(as.w + ed.w + ad4.w));
            sm[0] += w_l.x; sm[1] += w_l.y; sm[2] += w_l.z; sm[3] += w_l.w;
        }
        int cnt = min(32, end - i0);
        int j = 0;
        for (; j + 1 < cnt; j += 2) {
            int sA = __shfl_sync(0xffffffffu, s_l, j);
            int sB = __shfl_sync(0xffffffffu, s_l, j + 1);
            float a0 = __shfl_sync(0xffffffffu, w_l.x, j);
            float a1 = __shfl_sync(0xffffffffu, w_l.y, j);
            float a2 = __shfl_sync(0xffffffffu, w_l.z, j);
            float a3 = __shfl_sync(0xffffffffu, w_l.w, j);
            float b0 = __shfl_sync(0xffffffffu, w_l.x, j + 1);
            float b1 = __shfl_sync(0xffffffffu, w_l.y, j + 1);
            float b2 = __shfl_sync(0xffffffffu, w_l.z, j + 1);
            float b3 = __shfl_sync(0xffffffffu, w_l.w, j + 1);
            float wA = (h == 0) ? a0 : (h == 1) ? a1 : (h == 2) ? a2 : a3;
            float wB = (h == 0) ? b0 : (h == 1) ? b1 : (h == 2) ? b2 : b3;
            uint4 qA = *(const uint4*)(d_h1h + (long)sA * 256 + gc);
            uint4 qB = *(const uint4*)(d_h1h + (long)sB * 256 + gc);
            float2 fA0 = __half22float2(*(__half2*)&qA.x);
            float2 fA1 = __half22float2(*(__half2*)&qA.y);
            float2 fA2 = __half22float2(*(__half2*)&qA.z);
            float2 fA3 = __half22float2(*(__half2*)&qA.w);
            float2 fB0 = __half22float2(*(__half2*)&qB.x);
            float2 fB1 = __half22float2(*(__half2*)&qB.y);
            float2 fB2 = __half22float2(*(__half2*)&qB.z);
            float2 fB3 = __half22float2(*(__half2*)&qB.w);
            acc[0] = fmaf(fA0.x, wA, fmaf(fB0.x, wB, acc[0]));
            acc[1] = fmaf(fA0.y, wA, fmaf(fB0.y, wB, acc[1]));
            acc[2] = fmaf(fA1.x, wA, fmaf(fB1.x, wB, acc[2]));
            acc[3] = fmaf(fA1.y, wA, fmaf(fB1.y, wB, acc[3]));
            acc[4] = fmaf(fA2.x, wA, fmaf(fB2.x, wB, acc[4]));
            acc[5] = fmaf(fA2.y, wA, fmaf(fB2.y, wB, acc[5]));
            acc[6] = fmaf(fA3.x, wA, fmaf(fB3.x, wB, acc[6]));
            acc[7] = fmaf(fA3.y, wA, fmaf(fB3.y, wB, acc[7]));
        }
        if (j < cnt) {
            int sA = __shfl_sync(0xffffffffu, s_l, j);
            float a0 = __shfl_sync(0xffffffffu, w_l.x, j);
            float a1 = __shfl_sync(0xffffffffu, w_l.y, j);
            float a2 = __shfl_sync(0xffffffffu, w_l.z, j);
            float a3 = __shfl_sync(0xffffffffu, w_l.w, j);
            float wA = (h == 0) ? a0 : (h == 1) ? a1 : (h == 2) ? a2 : a3;
            uint4 qA = *(const uint4*)(d_h1h + (long)sA * 256 + gc);
            float2 fA0 = __half22float2(*(__half2*)&qA.x);
            float2 fA1 = __half22float2(*(__half2*)&qA.y);
            float2 fA2 = __half22float2(*(__half2*)&qA.z);
            float2 fA3 = __half22float2(*(__half2*)&qA.w);
            acc[0] = fmaf(fA0.x, wA, acc[0]);
            acc[1] = fmaf(fA0.y, wA, acc[1]);
            acc[2] = fmaf(fA1.x, wA, acc[2]);
            acc[3] = fmaf(fA1.y, wA, acc[3]);
            acc[4] = fmaf(fA2.x, wA, acc[4]);
            acc[5] = fmaf(fA2.y, wA, acc[5]);
            acc[6] = fmaf(fA3.x, wA, acc[6]);
            acc[7] = fmaf(fA3.y, wA, acc[7]);
        }
    }
    #pragma unroll
    for (int hh = 0; hh < 4; hh++) sm[hh] = warpSumAll(sm[hh]);
    float inv = 1.f / (((h == 0) ? sm[0] : (h == 1) ? sm[1] : (h == 2) ? sm[2] : sm[3]) + 1e-16f);
    float* op = d_out1 + (long)n * 256 + gc;
    #pragma unroll
    for (int j = 0; j < 8; j++) op[j] = fmaxf(acc[j] * inv + bias[gc + j], 0.f);
}

// ---------------- GAT2 aggregate (single-pass) + fused gate logit ----------------
__global__ void gat2_agg_kernel(const float* __restrict__ bias,
                                const float* __restrict__ gW, const float* __restrict__ gb) {
    int n = (blockIdx.x * blockDim.x + threadIdx.x) >> 5;
    if (n >= NN) return;
    int lane = threadIdx.x & 31;
    int beg = d_off[n], end = d_off[n + 1];
    float ad = d_ad2[n];
    int gc = lane * 2;
    float a0 = 0.f, a1 = 0.f;
    float sm = 0.f;
    for (int i0 = beg; i0 < end; i0 += 32) {
        int i = i0 + lane;
        int s_l = 0;
        float w_l = 0.f;
        if (i < end) {
            s_l = d_srcp[i];
            w_l = __expf(leaky02(d_as2[s_l] + d_eadot2[i] + ad));
            sm += w_l;
        }
        int cnt = min(32, end - i0);
        int j = 0;
        for (; j + 1 < cnt; j += 2) {
            int sA = __shfl_sync(0xffffffffu, s_l, j);
            int sB = __shfl_sync(0xffffffffu, s_l, j + 1);
            float wA = __shfl_sync(0xffffffffu, w_l, j);
            float wB = __shfl_sync(0xffffffffu, w_l, j + 1);
            float2 pA = __half22float2(*(const __half2*)(d_h2h + (long)sA * 64 + gc));
            float2 pB = __half22float2(*(const __half2*)(d_h2h + (long)sB * 64 + gc));
            a0 = fmaf(pA.x, wA, fmaf(pB.x, wB, a0));
            a1 = fmaf(pA.y, wA, fmaf(pB.y, wB, a1));
        }
        if (j < cnt) {
            int sA = __shfl_sync(0xffffffffu, s_l, j);
            float wA = __shfl_sync(0xffffffffu, w_l, j);
            float2 pA = __half22float2(*(const __half2*)(d_h2h + (long)sA * 64 + gc));
            a0 = fmaf(pA.x, wA, a0);
            a1 = fmaf(pA.y, wA, a1);
        }
    }
    sm = warpSumAll(sm);
    float inv = 1.f / (sm + 1e-16f);
    float o0 = a0 * inv + bias[gc];
    float o1 = a1 * inv + bias[gc + 1];
    d_out2[(long)n * 64 + gc] = o0;
    d_out2[(long)n * 64 + gc + 1] = o1;
    float gv = o0 * gW[gc] + o1 * gW[gc + 1];
    gv = warpSumAll(gv);
    if (lane == 0) d_gate[n] = gv + gb[0];
}

// ---------------- pooling ----------------
__global__ void bbounds_kernel(const int* __restrict__ bv) {
    int n = blockIdx.x * blockDim.x + threadIdx.x;
    if (n >= NN) return;
    int b = bv[n];
    atomicMin(&d_bs[b], n);
    atomicMax(&d_be[b], n + 1);
}
__global__ void pool_kernel() {
    int b = blockIdx.x;
    int s = d_bs[b], e = d_be[b];
    __shared__ float sh[256];
    int t = threadIdx.x;
    if (e <= s) {
        if (t < 64) d_rel[b * 64 + t] = 0.f;
        return;
    }
    float m = -INFINITY;
    for (int n = s + t; n < e; n += 256) m = fmaxf(m, d_gate[n]);
    sh[t] = m;
    __syncthreads();
    for (int o = 128; o; o >>= 1) { if (t < o) sh[t] = fmaxf(sh[t], sh[t + o]); __syncthreads(); }
    m = sh[0];
    __syncthreads();
    float sum = 0.f;
    for (int n = s + t; n < e; n += 256) sum += __expf(d_gate[n] - m);
    sh[t] = sum;
    __syncthreads();
    for (int o = 128; o; o >>= 1) { if (t < o) sh[t] += sh[t + o]; __syncthreads(); }
    float inv = 1.f / (sh[0] + 1e-16f);
    __syncthreads();
    int g = t >> 6, c = t & 63;
    float acc = 0.f;
    for (int n = s + g; n < e; n += 4) {
        float w = __expf(d_gate[n] - m) * inv;
        acc = fmaf(w, d_out2[(long)n * 64 + c], acc);
    }
    sh[t] = acc;
    __syncthreads();
    if (g == 0) d_rel[b * 64 + c] = sh[c] + sh[c + 64] + sh[c + 128] + sh[c + 192];
}

// ---------------- classifier ----------------
__global__ void cls_kernel(const float* __restrict__ w1, const float* __restrict__ b1,
                           const float* __restrict__ w2, const float* __restrict__ b2,
                           float* __restrict__ out) {
    int b = blockIdx.x;
    int t = threadIdx.x;  // 64 threads
    __shared__ float comb[192];
    __shared__ float hid[64];
    for (int k = t; k < 192; k += 64)
        comb[k] = (k < 128) ? d_scene[b * 128 + k] : d_rel[b * 64 + (k - 128)];
    __syncthreads();
    float a = b1[t];
    #pragma unroll 4
    for (int k = 0; k < 192; k++) a = fmaf(comb[k], w1[k * 64 + t], a);
    hid[t] = fmaxf(a, 0.f);
    __syncthreads();
    if (t < 3) {
        float o = b2[t];
        #pragma unroll
        for (int k = 0; k < 64; k++) o = fmaf(hid[k], w2[k * 3 + t], o);
        out[b * 3 + t] = o;
    }
}

// ---------------- launch ----------------
extern "C" void kernel_launch(void* const* d_in, const int* in_sizes, int n_in,
                              void* d_out, int out_size) {
    const float* global_feat = (const float*)d_in[0];
    const float* x           = (const float*)d_in[1];
    const float* roi_feats   = (const float*)d_in[2];
    const int*   edge_index  = (const int*)d_in[3];
    const float* edge_attr   = (const float*)d_in[4];
    const int*   batch_vec   = (const int*)d_in[5];
    const float* roi_W   = (const float*)d_in[6];
    const float* roi_b   = (const float*)d_in[7];
    const float* scene_W = (const float*)d_in[8];
    const float* scene_b = (const float*)d_in[9];
    const float* g1_W   = (const float*)d_in[10];
    const float* g1_as  = (const float*)d_in[11];
    const float* g1_ad  = (const float*)d_in[12];
    const float* g1_We  = (const float*)d_in[13];
    const float* g1_ae  = (const float*)d_in[14];
    const float* g1_b   = (const float*)d_in[15];
    const float* g2_W   = (const float*)d_in[16];
    const float* g2_as  = (const float*)d_in[17];
    const float* g2_ad  = (const float*)d_in[18];
    const float* g2_We  = (const float*)d_in[19];
    const float* g2_ae  = (const float*)d_in[20];
    const float* g2_b   = (const float*)d_in[21];
    const float* gate_W = (const float*)d_in[22];
    const float* gate_b = (const float*)d_in[23];
    const float* cls1_W = (const float*)d_in[24];
    const float* cls1_b = (const float*)d_in[25];
    const float* cls2_W = (const float*)d_in[26];
    const float* cls2_b = (const float*)d_in[27];
    float* out = (float*)d_out;

    const int* src = edge_index;       // row 0
    const int* dst = edge_index + NE;  // row 1

    float *dscene, *dx77, *dout1, *das1, *dad1, *das2, *dad2;
    __half *dh1h, *dh2h;
    cudaGetSymbolAddress((void**)&dscene, d_scene);
    cudaGetSymbolAddress((void**)&dx77, d_x77);
    cudaGetSymbolAddress((void**)&dout1, d_out1);
    cudaGetSymbolAddress((void**)&dh1h, d_h1h);
    cudaGetSymbolAddress((void**)&dh2h, d_h2h);
    cudaGetSymbolAddress((void**)&das1, d_as1);
    cudaGetSymbolAddress((void**)&dad1, d_ad1);
    cudaGetSymbolAddress((void**)&das2, d_as2);
    cudaGetSymbolAddress((void**)&dad2, d_ad2);

    // fork-join: edge/CSR chain on a second stream; see round-6 notes.
    cudaStream_t s2;
    cudaStreamCreateWithFlags(&s2, cudaStreamNonBlocking);
    cudaEvent_t evFork, evJoin;
    cudaEventCreateWithFlags(&evFork, cudaEventDisableTiming);
    cudaEventCreateWithFlags(&evJoin, cudaEventDisableTiming);

    cudaEventRecord(evFork, 0);
    cudaStreamWaitEvent(s2, evFork, 0);

    // ---- stream s2: CSR build + permute/dots + batch bounds ----
    compute_we_kernel<<<1, 32, 0, s2>>>(g1_We, g1_ae, g2_We, g2_ae);
    init_kernel<<<NN / 256, 256, 0, s2>>>();
    hist_kernel<<<NE / 256, 256, 0, s2>>>(dst);
    blocksum_kernel<<<256, 256, 0, s2>>>();
    scanb_kernel<<<1, 256, 0, s2>>>();
    expand_kernel<<<256, 256, 0, s2>>>();
    scatter_kernel<<<NE / 256, 256, 0, s2>>>(dst);
    permute_kernel<<<NE / 256, 256, 0, s2>>>(src, edge_attr);
    bbounds_kernel<<<NN / 256, 256, 0, s2>>>(batch_vec);
    cudaEventRecord(evJoin, s2);

    // ---- capture stream: projections + h1 GEMM (fused att dots) ----
    gemm_tf32_kernel<false, true, false, true, false><<<dim3(2, 4), 256>>>(
        global_feat, scene_W, scene_b, dscene, nullptr,
        nullptr, nullptr, nullptr, nullptr, 0, NB, 512, 128, 128, 0);
    gemm_tf32_kernel<true, true, false, true, false><<<dim3(1, NN / 128), 256>>>(
        roi_feats, roi_W, roi_b, dx77, nullptr,
        nullptr, nullptr, nullptr, nullptr, 0, NN, 256, 64, 77, 13);
    copyx_kernel<<<(NN * 13 + 255) / 256, 256>>>(x);
    // h1 = x77 @ g1_W : fp16 out + fused per-head att dots (block x = head)
    gemm_tf32_kernel<false, false, true, false, true><<<dim3(4, NN / 128), 256>>>(
        dx77, g1_W, nullptr, nullptr, dh1h,
        g1_as, g1_ad, das1, dad1, 4, NN, 77, 256, 256, 0);

    // join: aggregation needs CSR + permuted payload + attention dots
    cudaStreamWaitEvent(0, evJoin, 0);

    gat1_agg_kernel<<<NN / 8, 256>>>(g1_b);

    // h2 = out1 @ g2_W : fp16 out + fused att dots (single head)
    gemm_tf32_kernel<false, false, true, false, true><<<dim3(1, NN / 128), 256>>>(
        dout1, g2_W, nullptr, nullptr, dh2h,
        g2_as, g2_ad, das2, dad2, 1, NN, 256, 64, 64, 0);

    gat2_agg_kernel<<<NN / 8, 256>>>(g2_b, gate_W, gate_b);

    pool_kernel<<<NB, 256>>>();
    cls_kernel<<<NB, 64>>>(cls1_W, cls1_b, cls2_W, cls2_b, out);
}

// round 14
// speedup vs baseline: 1.1723x; 1.1723x over previous
#include <cuda_runtime.h>
#include <cuda_fp16.h>
#include <math.h>
#include <stdint.h>

#define NN 65536
#define NE 1048576
#define NB 512

// ---------------- scratch (static __device__, no allocation) ----------------
__device__ float  d_x77[NN * 77];
__device__ __half d_h1h[NN * 256];
__device__ __half d_out1h[NN * 256];
__device__ float  d_as1[NN * 4];
__device__ float  d_ad1[NN * 4];
__device__ __half d_h2h[NN * 64];
__device__ float  d_out2[NN * 64];
__device__ float  d_as2[NN];
__device__ float  d_ad2[NN];
__device__ int    d_deg[NN];
__device__ int    d_off[NN + 1];
__device__ int    d_cur[NN];
__device__ int    d_bsum[256];
__device__ int    d_boff[256];
__device__ int    d_perm[NE];      // CSR position -> edge id
__device__ int    d_srcp[NE];      // src node id, CSR-permuted
__device__ float4 d_eadot1[NE];    // CSR-permuted edge-attr logit dots
__device__ float  d_eadot2[NE];
__device__ float  d_scene[NB * 128];
__device__ float  d_gate[NN];
__device__ int    d_bs[NB];
__device__ int    d_be[NB];
__device__ float  d_rel[NB * 64];
__device__ float  d_we1[20];   // [k][h] k<5, h<4
__device__ float  d_we2[5];

// ---------------- helpers ----------------
__device__ __forceinline__ float warpSumAll(float v) {
    #pragma unroll
    for (int o = 16; o; o >>= 1) v += __shfl_xor_sync(0xffffffffu, v, o);
    return v;
}
__device__ __forceinline__ float leaky02(float v) { return v > 0.f ? v : 0.2f * v; }

__device__ __forceinline__ uint32_t f2tf32(float f) {
    uint32_t r;
    asm("cvt.rna.tf32.f32 %0, %1;" : "=r"(r) : "f"(f));
    return r;
}
__device__ __forceinline__ void mma_tf32(float c[4], const uint32_t a[4], const uint32_t b[2]) {
    asm volatile(
        "mma.sync.aligned.m16n8k8.row.col.f32.tf32.tf32.f32 "
        "{%0,%1,%2,%3}, {%4,%5,%6,%7}, {%8,%9}, {%0,%1,%2,%3};"
        : "+f"(c[0]), "+f"(c[1]), "+f"(c[2]), "+f"(c[3])
        : "r"(a[0]), "r"(a[1]), "r"(a[2]), "r"(a[3]), "r"(b[0]), "r"(b[1]));
}

// ---------------- tiny precompute: We . att_edge per head ----------------
__global__ void compute_we_kernel(const float* __restrict__ g1We, const float* __restrict__ g1ae,
                                  const float* __restrict__ g2We, const float* __restrict__ g2ae) {
    int t = threadIdx.x;
    if (t < 20) {
        int k = t / 4, h = t % 4;
        float s = 0.f;
        for (int c = 0; c < 64; c++) s += g1We[k * 256 + h * 64 + c] * g1ae[h * 64 + c];
        d_we1[k * 4 + h] = s;
    } else if (t < 25) {
        int k = t - 20;
        float s = 0.f;
        for (int c = 0; c < 64; c++) s += g2We[k * 64 + c] * g2ae[c];
        d_we2[k] = s;
    }
}

// ---------------- tf32 tensor-core GEMM ----------------
// Block tile 128(M) x 64(N) x 32(K). 8 warps 4x2; warp tile 32x32.
// AT: float or __half input A. Outputs: fp32 C (WF32) and/or fp16 Ch (HOUT).
template <bool RELU, bool BIAS, bool HOUT, bool WF32, typename AT>
__global__ void gemm_tf32_kernel(const AT* __restrict__ A, const float* __restrict__ W,
                                 const float* __restrict__ bias, float* __restrict__ C,
                                 __half* __restrict__ Ch,
                                 int M, int K, int Nc, int ldc, int coff) {
    __shared__ uint32_t As[128][36];  // [m][k]
    __shared__ uint32_t Ws[32][72];   // [k][n]
    int tid = threadIdx.x;
    int warp = tid >> 5, lane = tid & 31;
    int wm = warp >> 1, wn = warp & 1;
    int row0 = blockIdx.y * 128, col0 = blockIdx.x * 64;
    int gr = lane >> 2, gc = lane & 3;

    float acc[2][4][4];
    #pragma unroll
    for (int mt = 0; mt < 2; mt++)
        #pragma unroll
        for (int nt = 0; nt < 4; nt++)
            #pragma unroll
            for (int f = 0; f < 4; f++) acc[mt][nt][f] = 0.f;

    int kTiles = (K + 31) >> 5;
    for (int kt = 0; kt < kTiles; kt++) {
        int k0 = kt << 5;
        #pragma unroll
        for (int j = 0; j < 16; j++) {
            int idx = tid + j * 256;
            int m = idx >> 5, k = idx & 31;
            float v = 0.f;
            if (k0 + k < K) v = (float)A[(long)(row0 + m) * K + k0 + k];
            As[m][k] = f2tf32(v);
        }
        #pragma unroll
        for (int j = 0; j < 8; j++) {
            int idx = tid + j * 256;
            int k = idx >> 6, n = idx & 63;
            float v = (k0 + k < K) ? W[(long)(k0 + k) * Nc + col0 + n] : 0.f;
            Ws[k][n] = f2tf32(v);
        }
        __syncthreads();
        #pragma unroll
        for (int ks = 0; ks < 4; ks++) {
            int kb = ks << 3;
            uint32_t a[2][4];
            #pragma unroll
            for (int mt = 0; mt < 2; mt++) {
                int mr = wm * 32 + mt * 16 + gr;
                a[mt][0] = As[mr][kb + gc];
                a[mt][1] = As[mr + 8][kb + gc];
                a[mt][2] = As[mr][kb + gc + 4];
                a[mt][3] = As[mr + 8][kb + gc + 4];
            }
            uint32_t b[4][2];
            #pragma unroll
            for (int nt = 0; nt < 4; nt++) {
                int nc = wn * 32 + nt * 8 + gr;
                b[nt][0] = Ws[kb + gc][nc];
                b[nt][1] = Ws[kb + gc + 4][nc];
            }
            #pragma unroll
            for (int mt = 0; mt < 2; mt++)
                #pragma unroll
                for (int nt = 0; nt < 4; nt++)
                    mma_tf32(acc[mt][nt], a[mt], b[nt]);
        }
        __syncthreads();
    }
    #pragma unroll
    for (int mt = 0; mt < 2; mt++) {
        int r0 = row0 + wm * 32 + mt * 16 + gr;
        #pragma unroll
        for (int nt = 0; nt < 4; nt++) {
            int cc = col0 + wn * 32 + nt * 8 + gc * 2;
            float b0 = BIAS ? bias[cc] : 0.f;
            float b1 = BIAS ? bias[cc + 1] : 0.f;
            float v0 = acc[mt][nt][0] + b0;
            float v1 = acc[mt][nt][1] + b1;
            float v2 = acc[mt][nt][2] + b0;
            float v3 = acc[mt][nt][3] + b1;
            if (RELU) { v0 = fmaxf(v0, 0.f); v1 = fmaxf(v1, 0.f); v2 = fmaxf(v2, 0.f); v3 = fmaxf(v3, 0.f); }
            if (WF32) {
                C[(long)r0 * ldc + coff + cc]           = v0;
                C[(long)r0 * ldc + coff + cc + 1]       = v1;
                C[(long)(r0 + 8) * ldc + coff + cc]     = v2;
                C[(long)(r0 + 8) * ldc + coff + cc + 1] = v3;
            }
            if (HOUT) {
                *(__half2*)(Ch + (long)r0 * ldc + cc)       = __floats2half2_rn(v0, v1);
                *(__half2*)(Ch + (long)(r0 + 8) * ldc + cc) = __floats2half2_rn(v2, v3);
            }
        }
    }
}

// ---------------- copy x (13 cols) into x77 ----------------
__global__ void copyx_kernel(const float* __restrict__ x) {
    int idx = blockIdx.x * blockDim.x + threadIdx.x;
    if (idx >= NN * 13) return;
    int n = idx / 13, k = idx - n * 13;
    d_x77[n * 77 + k] = x[idx];
}

// ---------------- per-node attention dots (H=4, fp16 input) ----------------
__global__ void as_ad_h4_kernel(const float* __restrict__ asrc, const float* __restrict__ adst) {
    int w = (blockIdx.x * blockDim.x + threadIdx.x) >> 5;
    if (w >= NN) return;
    int lane = threadIdx.x & 31;
    int gc = lane * 8;
    uint4 q = *(const uint4*)(d_h1h + (long)w * 256 + gc);
    float2 f0 = __half22float2(*(__half2*)&q.x);
    float2 f1 = __half22float2(*(__half2*)&q.y);
    float2 f2 = __half22float2(*(__half2*)&q.z);
    float2 f3 = __half22float2(*(__half2*)&q.w);
    const float4* sp = (const float4*)(asrc + gc);
    float4 s0 = sp[0], s1 = sp[1];
    const float4* dp = (const float4*)(adst + gc);
    float4 q0 = dp[0], q1 = dp[1];
    float ps = f0.x * s0.x + f0.y * s0.y + f1.x * s0.z + f1.y * s0.w +
               f2.x * s1.x + f2.y * s1.y + f3.x * s1.z + f3.y * s1.w;
    float pd = f0.x * q0.x + f0.y * q0.y + f1.x * q0.z + f1.y * q0.w +
               f2.x * q1.x + f2.y * q1.y + f3.x * q1.z + f3.y * q1.w;
    #pragma unroll
    for (int o = 4; o; o >>= 1) {
        ps += __shfl_xor_sync(0xffffffffu, ps, o);
        pd += __shfl_xor_sync(0xffffffffu, pd, o);
    }
    if ((lane & 7) == 0) {
        int h = lane >> 3;
        d_as1[w * 4 + h] = ps;
        d_ad1[w * 4 + h] = pd;
    }
}

// ---------------- per-node attention dots (H=1, fp16 input) ----------------
__global__ void as_ad_h1_kernel(const float* __restrict__ asrc, const float* __restrict__ adst) {
    int w = (blockIdx.x * blockDim.x + threadIdx.x) >> 5;
    if (w >= NN) return;
    int lane = threadIdx.x & 31;
    int gc = lane * 2;
    float2 p = __half22float2(*(const __half2*)(d_h2h + (long)w * 64 + gc));
    float2 s = *(const float2*)(asrc + gc);
    float2 q = *(const float2*)(adst + gc);
    float ps = p.x * s.x + p.y * s.y;
    float pd = p.x * q.x + p.y * q.y;
    ps = warpSumAll(ps);
    pd = warpSumAll(pd);
    if (lane == 0) { d_as2[w] = ps; d_ad2[w] = pd; }
}

// ---------------- CSR build (hierarchical scan) ----------------
__global__ void init_kernel() {
    int i = blockIdx.x * blockDim.x + threadIdx.x;
    if (i < NN) d_deg[i] = 0;
    if (i < NB) { d_bs[i] = NN; d_be[i] = 0; }
}
__global__ void hist_kernel(const int* __restrict__ dst) {
    int e = blockIdx.x * blockDim.x + threadIdx.x;
    if (e < NE) atomicAdd(&d_deg[dst[e]], 1);
}
__global__ void blocksum_kernel() {
    __shared__ int sh[8];
    int t = threadIdx.x;
    int v = d_deg[blockIdx.x * 256 + t];
    #pragma unroll
    for (int o = 16; o; o >>= 1) v += __shfl_xor_sync(0xffffffffu, v, o);
    if ((t & 31) == 0) sh[t >> 5] = v;
    __syncthreads();
    if (t < 8) {
        int s = sh[t];
        #pragma unroll
        for (int o = 4; o; o >>= 1) s += __shfl_xor_sync(0xffu, s, o);
        if (t == 0) d_bsum[blockIdx.x] = s;
    }
}
__global__ void scanb_kernel() {
    __shared__ int sh[256];
    int t = threadIdx.x;
    int v = d_bsum[t];
    sh[t] = v;
    __syncthreads();
    #pragma unroll
    for (int o = 1; o < 256; o <<= 1) {
        int u = (t >= o) ? sh[t - o] : 0;
        __syncthreads();
        sh[t] += u;
        __syncthreads();
    }
    d_boff[t] = sh[t] - v;
}
__global__ void expand_kernel() {
    __shared__ int sh[256];
    int t = threadIdx.x;
    int n = blockIdx.x * 256 + t;
    int v = d_deg[n];
    sh[t] = v;
    __syncthreads();
    #pragma unroll
    for (int o = 1; o < 256; o <<= 1) {
        int u = (t >= o) ? sh[t - o] : 0;
        __syncthreads();
        sh[t] += u;
        __syncthreads();
    }
    int off = d_boff[blockIdx.x] + sh[t] - v;
    d_off[n] = off;
    d_cur[n] = off;
    if (n == NN - 1) d_off[NN] = NE;
}
__global__ void scatter_kernel(const int* __restrict__ dst) {
    int e = blockIdx.x * blockDim.x + threadIdx.x;
    if (e >= NE) return;
    int p = atomicAdd(&d_cur[dst[e]], 1);
    d_perm[p] = e;
}
// gather-permute with fused edge-attr dots: coalesced writes, random reads
__global__ void permute_kernel(const int* __restrict__ src, const float* __restrict__ ea) {
    int i = blockIdx.x * blockDim.x + threadIdx.x;
    if (i >= NE) return;
    int e = d_perm[i];
    float a[5];
    #pragma unroll
    for (int k = 0; k < 5; k++) a[k] = ea[e * 5 + k];
    float4 ed = make_float4(0.f, 0.f, 0.f, 0.f);
    float e2 = 0.f;
    #pragma unroll
    for (int k = 0; k < 5; k++) {
        ed.x = fmaf(a[k], d_we1[k * 4 + 0], ed.x);
        ed.y = fmaf(a[k], d_we1[k * 4 + 1], ed.y);
        ed.z = fmaf(a[k], d_we1[k * 4 + 2], ed.z);
        ed.w = fmaf(a[k], d_we1[k * 4 + 3], ed.w);
        e2   = fmaf(a[k], d_we2[k], e2);
    }
    d_srcp[i] = src[e];
    d_eadot1[i] = ed;
    d_eadot2[i] = e2;
}

// ---------------- GAT1 aggregate: single-pass unnormalized softmax ----------------
__global__ void gat1_agg_kernel(const float* __restrict__ bias) {
    int n = (blockIdx.x * blockDim.x + threadIdx.x) >> 5;
    if (n >= NN) return;
    int lane = threadIdx.x & 31;
    int beg = d_off[n], end = d_off[n + 1];
    float4 ad4 = *(const float4*)(d_ad1 + n * 4);
    int h = lane >> 3;
    int gc = lane * 8;
    float acc[8] = {0.f, 0.f, 0.f, 0.f, 0.f, 0.f, 0.f, 0.f};
    float sm[4] = {0.f, 0.f, 0.f, 0.f};
    for (int i0 = beg; i0 < end; i0 += 32) {
        int i = i0 + lane;
        int s_l = 0;
        float4 w_l = make_float4(0.f, 0.f, 0.f, 0.f);
        if (i < end) {
            s_l = d_srcp[i];
            float4 ed = d_eadot1[i];
            float4 as = *(const float4*)(d_as1 + s_l * 4);
            w_l.x = __expf(leaky02(as.x + ed.x + ad4.x));
            w_l.y = __expf(leaky02(as.y + ed.y + ad4.y));
            w_l.z = __expf(leaky02(as.z + ed.z + ad4.z));
            w_l.w = __expf(leaky02(as.w + ed.w + ad4.w));
            sm[0] += w_l.x; sm[1] += w_l.y; sm[2] += w_l.z; sm[3] += w_l.w;
        }
        int cnt = min(32, end - i0);
        int j = 0;
        for (; j + 1 < cnt; j += 2) {
            int sA = __shfl_sync(0xffffffffu, s_l, j);
            int sB = __shfl_sync(0xffffffffu, s_l, j + 1);
            float a0 = __shfl_sync(0xffffffffu, w_l.x, j);
            float a1 = __shfl_sync(0xffffffffu, w_l.y, j);
            float a2 = __shfl_sync(0xffffffffu, w_l.z, j);
            float a3 = __shfl_sync(0xffffffffu, w_l.w, j);
            float b0 = __shfl_sync(0xffffffffu, w_l.x, j + 1);
            float b1 = __shfl_sync(0xffffffffu, w_l.y, j + 1);
            float b2 = __shfl_sync(0xffffffffu, w_l.z, j + 1);
            float b3 = __shfl_sync(0xffffffffu, w_l.w, j + 1);
            float wA = (h == 0) ? a0 : (h == 1) ? a1 : (h == 2) ? a2 : a3;
            float wB = (h == 0) ? b0 : (h == 1) ? b1 : (h == 2) ? b2 : b3;
            uint4 qA = *(const uint4*)(d_h1h + (long)sA * 256 + gc);
            uint4 qB = *(const uint4*)(d_h1h + (long)sB * 256 + gc);
            float2 fA0 = __half22float2(*(__half2*)&qA.x);
            float2 fA1 = __half22float2(*(__half2*)&qA.y);
            float2 fA2 = __half22float2(*(__half2*)&qA.z);
            float2 fA3 = __half22float2(*(__half2*)&qA.w);
            float2 fB0 = __half22float2(*(__half2*)&qB.x);
            float2 fB1 = __half22float2(*(__half2*)&qB.y);
            float2 fB2 = __half22float2(*(__half2*)&qB.z);
            float2 fB3 = __half22float2(*(__half2*)&qB.w);
            acc[0] = fmaf(fA0.x, wA, fmaf(fB0.x, wB, acc[0]));
            acc[1] = fmaf(fA0.y, wA, fmaf(fB0.y, wB, acc[1]));
            acc[2] = fmaf(fA1.x, wA, fmaf(fB1.x, wB, acc[2]));
            acc[3] = fmaf(fA1.y, wA, fmaf(fB1.y, wB, acc[3]));
            acc[4] = fmaf(fA2.x, wA, fmaf(fB2.x, wB, acc[4]));
            acc[5] = fmaf(fA2.y, wA, fmaf(fB2.y, wB, acc[5]));
            acc[6] = fmaf(fA3.x, wA, fmaf(fB3.x, wB, acc[6]));
            acc[7] = fmaf(fA3.y, wA, fmaf(fB3.y, wB, acc[7]));
        }
        if (j < cnt) {
            int sA = __shfl_sync(0xffffffffu, s_l, j);
            float a0 = __shfl_sync(0xffffffffu, w_l.x, j);
            float a1 = __shfl_sync(0xffffffffu, w_l.y, j);
            float a2 = __shfl_sync(0xffffffffu, w_l.z, j);
            float a3 = __shfl_sync(0xffffffffu, w_l.w, j);
            float wA = (h == 0) ? a0 : (h == 1) ? a1 : (h == 2) ? a2 : a3;
            uint4 qA = *(const uint4*)(d_h1h + (long)sA * 256 + gc);
            float2 fA0 = __half22float2(*(__half2*)&qA.x);
            float2 fA1 = __half22float2(*(__half2*)&qA.y);
            float2 fA2 = __half22float2(*(__half2*)&qA.z);
            float2 fA3 = __half22float2(*(__half2*)&qA.w);
            acc[0] = fmaf(fA0.x, wA, acc[0]);
            acc[1] = fmaf(fA0.y, wA, acc[1]);
            acc[2] = fmaf(fA1.x, wA, acc[2]);
            acc[3] = fmaf(fA1.y, wA, acc[3]);
            acc[4] = fmaf(fA2.x, wA, acc[4]);
            acc[5] = fmaf(fA2.y, wA, acc[5]);
            acc[6] = fmaf(fA3.x, wA, acc[6]);
            acc[7] = fmaf(fA3.y, wA, acc[7]);
        }
    }
    #pragma unroll
    for (int hh = 0; hh < 4; hh++) sm[hh] = warpSumAll(sm[hh]);
    float inv = 1.f / (((h == 0) ? sm[0] : (h == 1) ? sm[1] : (h == 2) ? sm[2] : sm[3]) + 1e-16f);
    __half* op = d_out1h + (long)n * 256 + gc;
    #pragma unroll
    for (int j = 0; j < 4; j++) {
        float v0 = fmaxf(acc[j * 2] * inv + bias[gc + j * 2], 0.f);
        float v1 = fmaxf(acc[j * 2 + 1] * inv + bias[gc + j * 2 + 1], 0.f);
        *(__half2*)(op + j * 2) = __floats2half2_rn(v0, v1);
    }
}

// ---------------- GAT2 aggregate (single-pass) + fused gate logit ----------------
__global__ void gat2_agg_kernel(const float* __restrict__ bias,
                                const float* __restrict__ gW, const float* __restrict__ gb) {
    int n = (blockIdx.x * blockDim.x + threadIdx.x) >> 5;
    if (n >= NN) return;
    int lane = threadIdx.x & 31;
    int beg = d_off[n], end = d_off[n + 1];
    float ad = d_ad2[n];
    int gc = lane * 2;
    float a0 = 0.f, a1 = 0.f;
    float sm = 0.f;
    for (int i0 = beg; i0 < end; i0 += 32) {
        int i = i0 + lane;
        int s_l = 0;
        float w_l = 0.f;
        if (i < end) {
            s_l = d_srcp[i];
            w_l = __expf(leaky02(d_as2[s_l] + d_eadot2[i] + ad));
            sm += w_l;
        }
        int cnt = min(32, end - i0);
        int j = 0;
        for (; j + 1 < cnt; j += 2) {
            int sA = __shfl_sync(0xffffffffu, s_l, j);
            int sB = __shfl_sync(0xffffffffu, s_l, j + 1);
            float wA = __shfl_sync(0xffffffffu, w_l, j);
            float wB = __shfl_sync(0xffffffffu, w_l, j + 1);
            float2 pA = __half22float2(*(const __half2*)(d_h2h + (long)sA * 64 + gc));
            float2 pB = __half22float2(*(const __half2*)(d_h2h + (long)sB * 64 + gc));
            a0 = fmaf(pA.x, wA, fmaf(pB.x, wB, a0));
            a1 = fmaf(pA.y, wA, fmaf(pB.y, wB, a1));
        }
        if (j < cnt) {
            int sA = __shfl_sync(0xffffffffu, s_l, j);
            float wA = __shfl_sync(0xffffffffu, w_l, j);
            float2 pA = __half22float2(*(const __half2*)(d_h2h + (long)sA * 64 + gc));
            a0 = fmaf(pA.x, wA, a0);
            a1 = fmaf(pA.y, wA, a1);
        }
    }
    sm = warpSumAll(sm);
    float inv = 1.f / (sm + 1e-16f);
    float o0 = a0 * inv + bias[gc];
    float o1 = a1 * inv + bias[gc + 1];
    d_out2[(long)n * 64 + gc] = o0;
    d_out2[(long)n * 64 + gc + 1] = o1;
    float gv = o0 * gW[gc] + o1 * gW[gc + 1];
    gv = warpSumAll(gv);
    if (lane == 0) d_gate[n] = gv + gb[0];
}

// ---------------- pooling ----------------
__global__ void bbounds_kernel(const int* __restrict__ bv) {
    int n = blockIdx.x * blockDim.x + threadIdx.x;
    if (n >= NN) return;
    int b = bv[n];
    atomicMin(&d_bs[b], n);
    atomicMax(&d_be[b], n + 1);
}
__global__ void pool_kernel() {
    int b = blockIdx.x;
    int s = d_bs[b], e = d_be[b];
    __shared__ float sh[256];
    int t = threadIdx.x;
    if (e <= s) {
        if (t < 64) d_rel[b * 64 + t] = 0.f;
        return;
    }
    float m = -INFINITY;
    for (int n = s + t; n < e; n += 256) m = fmaxf(m, d_gate[n]);
    sh[t] = m;
    __syncthreads();
    for (int o = 128; o; o >>= 1) { if (t < o) sh[t] = fmaxf(sh[t], sh[t + o]); __syncthreads(); }
    m = sh[0];
    __syncthreads();
    float sum = 0.f;
    for (int n = s + t; n < e; n += 256) sum += __expf(d_gate[n] - m);
    sh[t] = sum;
    __syncthreads();
    for (int o = 128; o; o >>= 1) { if (t < o) sh[t] += sh[t + o]; __syncthreads(); }
    float inv = 1.f / (sh[0] + 1e-16f);
    __syncthreads();
    int g = t >> 6, c = t & 63;
    float acc = 0.f;
    for (int n = s + g; n < e; n += 4) {
        float w = __expf(d_gate[n] - m) * inv;
        acc = fmaf(w, d_out2[(long)n * 64 + c], acc);
    }
    sh[t] = acc;
    __syncthreads();
    if (g == 0) d_rel[b * 64 + c] = sh[c] + sh[c + 64] + sh[c + 128] + sh[c + 192];
}

// ---------------- classifier ----------------
__global__ void cls_kernel(const float* __restrict__ w1, const float* __restrict__ b1,
                           const float* __restrict__ w2, const float* __restrict__ b2,
                           float* __restrict__ out) {
    int b = blockIdx.x;
    int t = threadIdx.x;  // 64 threads
    __shared__ float comb[192];
    __shared__ float hid[64];
    for (int k = t; k < 192; k += 64)
        comb[k] = (k < 128) ? d_scene[b * 128 + k] : d_rel[b * 64 + (k - 128)];
    __syncthreads();
    float a = b1[t];
    #pragma unroll 4
    for (int k = 0; k < 192; k++) a = fmaf(comb[k], w1[k * 64 + t], a);
    hid[t] = fmaxf(a, 0.f);
    __syncthreads();
    if (t < 3) {
        float o = b2[t];
        #pragma unroll
        for (int k = 0; k < 64; k++) o = fmaf(hid[k], w2[k * 3 + t], o);
        out[b * 3 + t] = o;
    }
}

// ---------------- launch ----------------
extern "C" void kernel_launch(void* const* d_in, const int* in_sizes, int n_in,
                              void* d_out, int out_size) {
    const float* global_feat = (const float*)d_in[0];
    const float* x           = (const float*)d_in[1];
    const float* roi_feats   = (const float*)d_in[2];
    const int*   edge_index  = (const int*)d_in[3];
    const float* edge_attr   = (const float*)d_in[4];
    const int*   batch_vec   = (const int*)d_in[5];
    const float* roi_W   = (const float*)d_in[6];
    const float* roi_b   = (const float*)d_in[7];
    const float* scene_W = (const float*)d_in[8];
    const float* scene_b = (const float*)d_in[9];
    const float* g1_W   = (const float*)d_in[10];
    const float* g1_as  = (const float*)d_in[11];
    const float* g1_ad  = (const float*)d_in[12];
    const float* g1_We  = (const float*)d_in[13];
    const float* g1_ae  = (const float*)d_in[14];
    const float* g1_b   = (const float*)d_in[15];
    const float* g2_W   = (const float*)d_in[16];
    const float* g2_as  = (const float*)d_in[17];
    const float* g2_ad  = (const float*)d_in[18];
    const float* g2_We  = (const float*)d_in[19];
    const float* g2_ae  = (const float*)d_in[20];
    const float* g2_b   = (const float*)d_in[21];
    const float* gate_W = (const float*)d_in[22];
    const float* gate_b = (const float*)d_in[23];
    const float* cls1_W = (const float*)d_in[24];
    const float* cls1_b = (const float*)d_in[25];
    const float* cls2_W = (const float*)d_in[26];
    const float* cls2_b = (const float*)d_in[27];
    float* out = (float*)d_out;

    const int* src = edge_index;       // row 0
    const int* dst = edge_index + NE;  // row 1

    float *dscene, *dx77;
    __half *dh1h, *dh2h, *dout1h;
    cudaGetSymbolAddress((void**)&dscene, d_scene);
    cudaGetSymbolAddress((void**)&dx77, d_x77);
    cudaGetSymbolAddress((void**)&dh1h, d_h1h);
    cudaGetSymbolAddress((void**)&dh2h, d_h2h);
    cudaGetSymbolAddress((void**)&dout1h, d_out1h);

    // fork-join: edge/CSR chain on a second stream; see round-6 notes.
    cudaStream_t s2;
    cudaStreamCreateWithFlags(&s2, cudaStreamNonBlocking);
    cudaEvent_t evFork, evJoin;
    cudaEventCreateWithFlags(&evFork, cudaEventDisableTiming);
    cudaEventCreateWithFlags(&evJoin, cudaEventDisableTiming);

    cudaEventRecord(evFork, 0);
    cudaStreamWaitEvent(s2, evFork, 0);

    // ---- stream s2: CSR build + permute/dots + batch bounds ----
    compute_we_kernel<<<1, 32, 0, s2>>>(g1_We, g1_ae, g2_We, g2_ae);
    init_kernel<<<NN / 256, 256, 0, s2>>>();
    hist_kernel<<<NE / 256, 256, 0, s2>>>(dst);
    blocksum_kernel<<<256, 256, 0, s2>>>();
    scanb_kernel<<<1, 256, 0, s2>>>();
    expand_kernel<<<256, 256, 0, s2>>>();
    scatter_kernel<<<NE / 256, 256, 0, s2>>>(dst);
    permute_kernel<<<NE / 256, 256, 0, s2>>>(src, edge_attr);
    bbounds_kernel<<<NN / 256, 256, 0, s2>>>(batch_vec);
    cudaEventRecord(evJoin, s2);

    // ---- capture stream: projections + h1 GEMM + attention dots ----
    gemm_tf32_kernel<false, true, false, true, float><<<dim3(2, 4), 256>>>(
        global_feat, scene_W, scene_b, dscene, nullptr, NB, 512, 128, 128, 0);
    gemm_tf32_kernel<true, true, false, true, float><<<dim3(1, NN / 128), 256>>>(
        roi_feats, roi_W, roi_b, dx77, nullptr, NN, 256, 64, 77, 13);
    copyx_kernel<<<(NN * 13 + 255) / 256, 256>>>(x);
    // h1 = x77 @ g1_W : fp16 output only
    gemm_tf32_kernel<false, false, true, false, float><<<dim3(4, NN / 128), 256>>>(
        dx77, g1_W, nullptr, nullptr, dh1h, NN, 77, 256, 256, 0);
    as_ad_h4_kernel<<<NN / 8, 256>>>(g1_as, g1_ad);

    // join: aggregation needs CSR + permuted payload + attention dots
    cudaStreamWaitEvent(0, evJoin, 0);

    gat1_agg_kernel<<<NN / 8, 256>>>(g1_b);

    // h2 = out1(fp16) @ g2_W : fp16 output only
    gemm_tf32_kernel<false, false, true, false, __half><<<dim3(1, NN / 128), 256>>>(
        dout1h, g2_W, nullptr, nullptr, dh2h, NN, 256, 64, 64, 0);
    as_ad_h1_kernel<<<NN / 8, 256>>>(g2_as, g2_ad);

    gat2_agg_kernel<<<NN / 8, 256>>>(g2_b, gate_W, gate_b);

    pool_kernel<<<NB, 256>>>();
    cls_kernel<<<NB, 64>>>(cls1_W, cls1_b, cls2_W, cls2_b, out);
}